// round 13
// baseline (speedup 1.0000x reference)
#include <cuda_runtime.h>
#include <math_constants.h>
#include <cstdint>

// SubsetOperator soft k-hot (K=16, TAU=1), exp-domain, fixed shift (-10).
// TWO ROWS PER CTA, SLOT-INTERLEAVED: row A's fold->barrier->scalar chain is
// hidden under row B's update slot and vice versa. 1024 thr, 1 CTA/SM.
// Sign-flip renorm (R12): after each 2-iter body, b=-p1*t => b*b+b = -(next
// normalized state); state stays negated, sign absorbed into scalar constants.
// Folds: u32 fixed point (2^28), per-warp redux.sync.add.u32 + lane0 atomicAdd.

#define ROWS 4096
#define NCOL 8192
#define THREADS 1024
#define RP 4                 // u64 per row per thread (8 elems)
#define GRID 148
#define NRP (ROWS / 2)

typedef unsigned long long u64;
typedef unsigned int u32;

#define MUL2(d,a,b)    asm("mul.rn.f32x2 %0, %1, %2;"     : "=l"(d) : "l"(a), "l"(b))
#define ADD2(d,a,b)    asm("add.rn.f32x2 %0, %1, %2;"     : "=l"(d) : "l"(a), "l"(b))
#define FMA2(d,a,b,c)  asm("fma.rn.f32x2 %0, %1, %2, %3;" : "=l"(d) : "l"(a), "l"(b), "l"(c))
#define PACK2(d,lo,hi)   asm("mov.b64 %0, {%1, %2};" : "=l"(d) : "f"(lo), "f"(hi))
#define UNPACK2(lo,hi,s) asm("mov.b64 {%0, %1}, %2;" : "=f"(lo), "=f"(hi) : "l"(s))

__device__ __forceinline__ float rcp_fast(float x) {
    float r; asm("rcp.approx.f32 %0, %1;" : "=f"(r) : "f"(x)); return r;
}
__device__ __forceinline__ float ex2_fast(float x) {
    float r; asm("ex2.approx.f32 %0, %1;" : "=f"(r) : "f"(x)); return r;
}
__device__ __forceinline__ u32 f2u_rni(float x) {
    u32 u; asm("cvt.rni.u32.f32 %0, %1;" : "=r"(u) : "f"(x)); return u;
}
__device__ __forceinline__ float u2f(u32 u) {
    float x; asm("cvt.rn.f32.u32 %0, %1;" : "=f"(x) : "r"(u)); return x;
}
__device__ __forceinline__ u32 redux_add_u32(u32 v) {
    u32 d; asm("redux.sync.add.u32 %0, %1, 0xffffffff;" : "=r"(d) : "r"(v)); return d;
}

#define SCALE_F  268435456.0f
#define NSCALE_F -268435456.0f
#define ISCALE_F 3.725290298461914e-9f

__device__ __forceinline__ void cp16(u32 dst, const void* src) {
    asm volatile("cp.async.cg.shared.global [%0], [%1], 16;" :: "r"(dst), "l"(src));
}

// tile: [sA | sB | gA | gB], 32KB each = 128KB
__device__ __forceinline__ void prefetch_pair(const float* s, const float* gg,
                                              int rp, float* tile, int tid, bool valid) {
    if (valid) {
        const int rA = 2 * rp, rB = 2 * rp + 1;
        u32 ds = (u32)__cvta_generic_to_shared(tile);
        const float4* sA = (const float4*)(s  + (size_t)rA * NCOL);
        const float4* sB = (const float4*)(s  + (size_t)rB * NCOL);
        const float4* gA = (const float4*)(gg + (size_t)rA * NCOL);
        const float4* gB = (const float4*)(gg + (size_t)rB * NCOL);
#pragma unroll
        for (int c = 0; c < 2; c++) {
            const int i4 = tid + c * THREADS;
            cp16(ds + 0u * NCOL * 4u + (u32)i4 * 16u, sA + i4);
            cp16(ds + 1u * NCOL * 4u + (u32)i4 * 16u, sB + i4);
            cp16(ds + 2u * NCOL * 4u + (u32)i4 * 16u, gA + i4);
            cp16(ds + 3u * NCOL * 4u + (u32)i4 * 16u, gB + i4);
        }
    }
    asm volatile("cp.async.commit_group;");
}

__global__ void __launch_bounds__(THREADS, 1)
subset_op_kernel(const float* __restrict__ scores,
                 const float* __restrict__ g,
                 float* __restrict__ out) {
    extern __shared__ __align__(16) float tile[];     // 128 KB
    __shared__ __align__(16) float2 redfA[32];
    __shared__ __align__(16) float2 redfB[32];
    __shared__ __align__(8)  u32 acc[2][7][2];        // [row][body][A,B]

    const int tid  = threadIdx.x;
    const int lane = tid & 31;
    const int wid  = tid >> 5;
    const float L2E = 1.4426950408889634f;
    const float CC  = -10.0f * L2E;

    int rp = blockIdx.x;
    prefetch_pair(scores, g, rp, tile, tid, true);

    for (; rp < NRP; rp += GRID) {
        asm volatile("cp.async.wait_group 0;");
        __syncthreads();

        // ---- prologue: exp + (A,B) moment partials, both rows ----
        u64 tA[RP], nkA[RP], tB[RP], nkB[RP];
        u64 maA = 0ull, mbA = 0ull, maB = 0ull, mbB = 0ull;
        const float4* tsA = (const float4*)tile;
        const float4* tsB = (const float4*)(tile + NCOL);
        const float4* tgA = (const float4*)(tile + 2 * NCOL);
        const float4* tgB = (const float4*)(tile + 3 * NCOL);
#pragma unroll
        for (int c = 0; c < 2; c++) {
            const int i4 = tid + c * THREADS;
            float4 a  = tsA[i4], ga = tgA[i4];
            float e0 = ex2_fast(fmaf(a.x + ga.x, L2E, CC));
            float e1 = ex2_fast(fmaf(a.y + ga.y, L2E, CC));
            float e2 = ex2_fast(fmaf(a.z + ga.z, L2E, CC));
            float e3 = ex2_fast(fmaf(a.w + ga.w, L2E, CC));
            PACK2(tA[2 * c],     e0, e1);
            PACK2(tA[2 * c + 1], e2, e3);
            nkA[2 * c] = 0ull; nkA[2 * c + 1] = 0ull;
            ADD2(maA, maA, tA[2 * c]);
            ADD2(maA, maA, tA[2 * c + 1]);
            FMA2(mbA, tA[2 * c],     tA[2 * c],     mbA);
            FMA2(mbA, tA[2 * c + 1], tA[2 * c + 1], mbA);

            float4 b  = tsB[i4], gb = tgB[i4];
            float f0 = ex2_fast(fmaf(b.x + gb.x, L2E, CC));
            float f1 = ex2_fast(fmaf(b.y + gb.y, L2E, CC));
            float f2 = ex2_fast(fmaf(b.z + gb.z, L2E, CC));
            float f3 = ex2_fast(fmaf(b.w + gb.w, L2E, CC));
            PACK2(tB[2 * c],     f0, f1);
            PACK2(tB[2 * c + 1], f2, f3);
            nkB[2 * c] = 0ull; nkB[2 * c + 1] = 0ull;
            ADD2(maB, maB, tB[2 * c]);
            ADD2(maB, maB, tB[2 * c + 1]);
            FMA2(mbB, tB[2 * c],     tB[2 * c],     mbB);
            FMA2(mbB, tB[2 * c + 1], tB[2 * c + 1], mbB);
        }
        prefetch_pair(scores, g, rp + GRID, tile, tid, (rp + GRID) < NRP);

        // f32 warp reduction of packed (A,B) per row; lane0 -> smem
        {
            float lo, hi, x, y;
            u64 u;
            UNPACK2(lo, hi, maA); x = lo + hi;
            UNPACK2(lo, hi, mbA); y = lo + hi;
            PACK2(u, x, y);
#pragma unroll
            for (int o = 16; o > 0; o >>= 1) {
                u64 t = __shfl_xor_sync(0xffffffffu, u, o);
                ADD2(u, u, t);
            }
            if (lane == 0) { float2 q; UNPACK2(q.x, q.y, u); redfA[wid] = q; }
            UNPACK2(lo, hi, maB); x = lo + hi;
            UNPACK2(lo, hi, mbB); y = lo + hi;
            PACK2(u, x, y);
#pragma unroll
            for (int o = 16; o > 0; o >>= 1) {
                u64 t = __shfl_xor_sync(0xffffffffu, u, o);
                ADD2(u, u, t);
            }
            if (lane == 0) { float2 q; UNPACK2(q.x, q.y, u); redfB[wid] = q; }
        }
        if (tid < 28) ((u32*)acc)[tid] = 0u;
        __syncthreads();

        float AfA, BfA, AfB, BfB;
        {
            float2 v = redfA[lane];
            u64 u; PACK2(u, v.x, v.y);
#pragma unroll
            for (int o = 16; o > 0; o >>= 1) {
                u64 t = __shfl_xor_sync(0xffffffffu, u, o);
                ADD2(u, u, t);
            }
            UNPACK2(AfA, BfA, u);
            float2 w = redfB[lane];
            PACK2(u, w.x, w.y);
#pragma unroll
            for (int o = 16; o > 0; o >>= 1) {
                u64 t = __shfl_xor_sync(0xffffffffu, u, o);
                ADD2(u, u, t);
            }
            UNPACK2(AfB, BfB, u);
        }

        // ---- interleaved slots: bodies 0..6 with folds ----
#pragma unroll
        for (int r = 0; r < 7; r++) {
            const float sg = (r == 0) ? -1.0f : 1.0f;
            // slot A_r
            if (r > 0) {
                AfA = u2f(acc[0][r - 1][0]) * ISCALE_F;
                BfA = u2f(acc[0][r - 1][1]) * ISCALE_F;
            }
            {
                float p0 = rcp_fast(AfA);
                float Z1 = fmaf(-BfA, p0, AfA);
                float p1 = rcp_fast(Z1);
                u64 vv, ww;
                PACK2(vv, sg * p0, sg * p0);
                PACK2(ww, sg * p1, sg * p1);
                u64 fa = 0ull, fb = 0ull;
#pragma unroll
                for (int j = 0; j < RP; j++) {
                    u64 q;
                    MUL2(q, tA[j], vv);
                    ADD2(nkA[j], nkA[j], q);
                    FMA2(tA[j], q, tA[j], tA[j]);
                }
#pragma unroll
                for (int j = 0; j < RP; j++) {
                    u64 b;
                    MUL2(b, tA[j], ww);
                    ADD2(nkA[j], nkA[j], b);
                    FMA2(tA[j], b, b, b);     // -(renormalized next state)
                    ADD2(fa, fa, tA[j]);
                    FMA2(fb, tA[j], tA[j], fb);
                }
                float lo, hi, pa, pb;
                UNPACK2(lo, hi, fa); pa = lo + hi;
                UNPACK2(lo, hi, fb); pb = lo + hi;
                u32 ua = redux_add_u32(f2u_rni(pa * NSCALE_F));
                u32 ub = redux_add_u32(f2u_rni(pb * SCALE_F));
                if (lane == 0) {
                    atomicAdd(&acc[0][r][0], ua);
                    atomicAdd(&acc[0][r][1], ub);
                }
            }
            __syncthreads();
            // slot B_r
            if (r > 0) {
                AfB = u2f(acc[1][r - 1][0]) * ISCALE_F;
                BfB = u2f(acc[1][r - 1][1]) * ISCALE_F;
            }
            {
                float p0 = rcp_fast(AfB);
                float Z1 = fmaf(-BfB, p0, AfB);
                float p1 = rcp_fast(Z1);
                u64 vv, ww;
                PACK2(vv, sg * p0, sg * p0);
                PACK2(ww, sg * p1, sg * p1);
                u64 fa = 0ull, fb = 0ull;
#pragma unroll
                for (int j = 0; j < RP; j++) {
                    u64 q;
                    MUL2(q, tB[j], vv);
                    ADD2(nkB[j], nkB[j], q);
                    FMA2(tB[j], q, tB[j], tB[j]);
                }
#pragma unroll
                for (int j = 0; j < RP; j++) {
                    u64 b;
                    MUL2(b, tB[j], ww);
                    ADD2(nkB[j], nkB[j], b);
                    FMA2(tB[j], b, b, b);
                    ADD2(fa, fa, tB[j]);
                    FMA2(fb, tB[j], tB[j], fb);
                }
                float lo, hi, pa, pb;
                UNPACK2(lo, hi, fa); pa = lo + hi;
                UNPACK2(lo, hi, fb); pb = lo + hi;
                u32 ua = redux_add_u32(f2u_rni(pa * NSCALE_F));
                u32 ub = redux_add_u32(f2u_rni(pb * SCALE_F));
                if (lane == 0) {
                    atomicAdd(&acc[1][r][0], ua);
                    atomicAdd(&acc[1][r][1], ub);
                }
            }
            __syncthreads();
        }

        // ---- body 7 (iterA + final iter), both rows, no folds ----
        {
            float AfA7 = u2f(acc[0][6][0]) * ISCALE_F;
            float BfA7 = u2f(acc[0][6][1]) * ISCALE_F;
            float p0 = rcp_fast(AfA7);
            float Z1 = fmaf(-BfA7, p0, AfA7);
            float p1 = rcp_fast(Z1);
            u64 vv, ww;                        // sigma = +1 (state negated)
            PACK2(vv, p0, p0);
            PACK2(ww, p1, p1);
#pragma unroll
            for (int j = 0; j < RP; j++) {
                u64 q;
                MUL2(q, tA[j], vv);
                ADD2(nkA[j], nkA[j], q);
                FMA2(tA[j], q, tA[j], tA[j]);
            }
#pragma unroll
            for (int j = 0; j < RP; j++) {
                u64 q;
                MUL2(q, tA[j], ww);
                ADD2(nkA[j], nkA[j], q);
            }
            float AfB7 = u2f(acc[1][6][0]) * ISCALE_F;
            float BfB7 = u2f(acc[1][6][1]) * ISCALE_F;
            p0 = rcp_fast(AfB7);
            Z1 = fmaf(-BfB7, p0, AfB7);
            p1 = rcp_fast(Z1);
            PACK2(vv, p0, p0);
            PACK2(ww, p1, p1);
#pragma unroll
            for (int j = 0; j < RP; j++) {
                u64 q;
                MUL2(q, tB[j], vv);
                ADD2(nkB[j], nkB[j], q);
                FMA2(tB[j], q, tB[j], tB[j]);
            }
#pragma unroll
            for (int j = 0; j < RP; j++) {
                u64 q;
                MUL2(q, tB[j], ww);
                ADD2(nkB[j], nkB[j], q);
            }
        }

        // ---- store khot = -nk, both rows ----
        const int rA = 2 * rp, rB = 2 * rp + 1;
        float4* oA = (float4*)(out + (size_t)rA * NCOL);
        float4* oB = (float4*)(out + (size_t)rB * NCOL);
#pragma unroll
        for (int c = 0; c < 2; c++) {
            const int i4 = tid + c * THREADS;
            float a0, a1, a2, a3;
            UNPACK2(a0, a1, nkA[2 * c]);
            UNPACK2(a2, a3, nkA[2 * c + 1]);
            float4 va; va.x = -a0; va.y = -a1; va.z = -a2; va.w = -a3;
            oA[i4] = va;
            UNPACK2(a0, a1, nkB[2 * c]);
            UNPACK2(a2, a3, nkB[2 * c + 1]);
            float4 vb; vb.x = -a0; vb.y = -a1; vb.z = -a2; vb.w = -a3;
            oB[i4] = vb;
        }
    }
}

extern "C" void kernel_launch(void* const* d_in, const int* in_sizes, int n_in,
                              void* d_out, int out_size) {
    const float* scores = (const float*)d_in[0];
    const float* g      = (const float*)d_in[1];
    float* out          = (float*)d_out;
    cudaFuncSetAttribute(subset_op_kernel,
                         cudaFuncAttributeMaxDynamicSharedMemorySize, 4 * NCOL * 4);
    subset_op_kernel<<<GRID, THREADS, 4 * NCOL * 4>>>(scores, g, out);
}

// round 15
// speedup vs baseline: 1.3107x; 1.3107x over previous
#include <cuda_runtime.h>
#include <math_constants.h>
#include <cstdint>

// SubsetOperator soft k-hot (K=16, TAU=1), exp-domain, fixed shift (-10).
// R12 base (512 thr, 2 CTAs/SM, sign-flip renorm, u32 redux+atomic folds)
// + STAGGERED PROLOGUE: row r+1's tile-wait/exp/moment pass runs in the middle
// of row r's body phase (independent work; MUFU pipe), its reduction barriers
// piggyback on row r's body barriers. Row boundary = store + register rotate.

#define ROWS 4096
#define NCOL 8192
#define THREADS 512
#define PAIRS 8
#define GRID 296

typedef unsigned long long u64;
typedef unsigned int u32;

#define MUL2(d,a,b)    asm("mul.rn.f32x2 %0, %1, %2;"     : "=l"(d) : "l"(a), "l"(b))
#define ADD2(d,a,b)    asm("add.rn.f32x2 %0, %1, %2;"     : "=l"(d) : "l"(a), "l"(b))
#define FMA2(d,a,b,c)  asm("fma.rn.f32x2 %0, %1, %2, %3;" : "=l"(d) : "l"(a), "l"(b), "l"(c))
#define PACK2(d,lo,hi)   asm("mov.b64 %0, {%1, %2};" : "=l"(d) : "f"(lo), "f"(hi))
#define UNPACK2(lo,hi,s) asm("mov.b64 {%0, %1}, %2;" : "=f"(lo), "=f"(hi) : "l"(s))

__device__ __forceinline__ float rcp_fast(float x) {
    float r; asm("rcp.approx.f32 %0, %1;" : "=f"(r) : "f"(x)); return r;
}
__device__ __forceinline__ float ex2_fast(float x) {
    float r; asm("ex2.approx.f32 %0, %1;" : "=f"(r) : "f"(x)); return r;
}
__device__ __forceinline__ u32 f2u_rni(float x) {
    u32 u; asm("cvt.rni.u32.f32 %0, %1;" : "=r"(u) : "f"(x)); return u;
}
__device__ __forceinline__ float u2f(u32 u) {
    float x; asm("cvt.rn.f32.u32 %0, %1;" : "=f"(x) : "r"(u)); return x;
}
__device__ __forceinline__ u32 redux_add_u32(u32 v) {
    u32 d; asm("redux.sync.add.u32 %0, %1, 0xffffffff;" : "=r"(d) : "r"(v)); return d;
}

#define SCALE_F  268435456.0f
#define NSCALE_F -268435456.0f
#define ISCALE_F 3.725290298461914e-9f

__device__ __forceinline__ void cp16(u32 dst, const void* src) {
    asm volatile("cp.async.cg.shared.global [%0], [%1], 16;" :: "r"(dst), "l"(src));
}

__device__ __forceinline__ void prefetch_row(const float* s, const float* gg,
                                             int row, float* tile, int tid, bool valid) {
    if (valid) {
        const float4* s4 = (const float4*)(s + (size_t)row * NCOL);
        const float4* g4 = (const float4*)(gg + (size_t)row * NCOL);
        u32 ds = (u32)__cvta_generic_to_shared(tile);
#pragma unroll
        for (int c = 0; c < 4; c++) {
            cp16(ds + (u32)(tid + c * THREADS) * 16u,                  s4 + tid + c * THREADS);
            cp16(ds + (u32)NCOL * 4u + (u32)(tid + c * THREADS) * 16u, g4 + tid + c * THREADS);
        }
    }
    asm volatile("cp.async.commit_group;");
}

// exp pass: read tile, produce packed state + (A,B) moment partials
__device__ __forceinline__ void exp_pass(const float* tile, int tid,
                                         u64* t, u64& ma, u64& mb) {
    const float4* ts4 = (const float4*)tile;
    const float4* tg4 = (const float4*)(tile + NCOL);
    const float L2E = 1.4426950408889634f;
    const float CC  = -10.0f * L2E;
    ma = 0ull; mb = 0ull;
#pragma unroll
    for (int c = 0; c < 4; c++) {
        const int i4 = tid + c * THREADS;
        float4 a = ts4[i4];
        float4 b = tg4[i4];
        float e0 = ex2_fast(fmaf(a.x + b.x, L2E, CC));
        float e1 = ex2_fast(fmaf(a.y + b.y, L2E, CC));
        float e2 = ex2_fast(fmaf(a.z + b.z, L2E, CC));
        float e3 = ex2_fast(fmaf(a.w + b.w, L2E, CC));
        PACK2(t[2 * c],     e0, e1);
        PACK2(t[2 * c + 1], e2, e3);
        ADD2(ma, ma, t[2 * c]);
        ADD2(ma, ma, t[2 * c + 1]);
        FMA2(mb, t[2 * c],     t[2 * c],     mb);
        FMA2(mb, t[2 * c + 1], t[2 * c + 1], mb);
    }
}

// warp-level packed (A,B) butterfly; lane0 writes float2 partial
__device__ __forceinline__ void warp_red_ab(u64 ma, u64 mb, float2* slot,
                                            int lane, int wid) {
    float lo, hi, x, y;
    UNPACK2(lo, hi, ma); x = lo + hi;
    UNPACK2(lo, hi, mb); y = lo + hi;
    u64 u; PACK2(u, x, y);
#pragma unroll
    for (int o = 16; o > 0; o >>= 1) {
        u64 tsh = __shfl_xor_sync(0xffffffffu, u, o);
        ADD2(u, u, tsh);
    }
    if (lane == 0) { float2 q; UNPACK2(q.x, q.y, u); slot[wid] = q; }
}

// cross-warp reduce of 16 float2 partials (every warp redundantly)
__device__ __forceinline__ void cross_red_ab(const float2* buf, int lane,
                                             float& A, float& B) {
    float2 v = buf[lane & 15];
    u64 u; PACK2(u, v.x, v.y);
#pragma unroll
    for (int o = 8; o > 0; o >>= 1) {
        u64 tsh = __shfl_xor_sync(0xffffffffu, u, o);
        ADD2(u, u, tsh);
    }
    UNPACK2(A, B, u);
}

__global__ void __launch_bounds__(THREADS, 2)
subset_op_kernel(const float* __restrict__ scores,
                 const float* __restrict__ g,
                 float* __restrict__ out) {
    extern __shared__ __align__(16) float tile[];     // 64 KB
    __shared__ __align__(16) float2 redf[16];
    __shared__ __align__(8)  u32 acc[2][7][2];

    const int tid  = threadIdx.x;
    const int lane = tid & 31;
    const int wid  = tid >> 5;

    int row = blockIdx.x;
    prefetch_row(scores, g, row, tile, tid, true);

    // ---- startup prologue for the first row ----
    u64 t[PAIRS], nk[PAIRS];
    float Af, Bf;
    {
        asm volatile("cp.async.wait_group 0;");
        __syncthreads();
        if (tid < 14) (&acc[0][0][0])[tid] = 0u;      // zero bank 0
        u64 ma, mb;
        exp_pass(tile, tid, t, ma, mb);
#pragma unroll
        for (int j = 0; j < PAIRS; j++) nk[j] = 0ull;
        prefetch_row(scores, g, row + GRID, tile, tid, (row + GRID) < ROWS);
        warp_red_ab(ma, mb, redf, lane, wid);
        __syncthreads();
        cross_red_ab(redf, lane, Af, Bf);
    }

    int bank = 0;
    for (; row < ROWS; row += GRID) {
        const bool hasNext = (row + GRID) < ROWS;
        u64 tn[PAIRS];
        float AfN = 0.0f, BfN = 0.0f;
        u32* const abank = &acc[bank][0][0];

        // ---- bodies 0..4 ----
#pragma unroll
        for (int r = 0; r < 5; r++) {
            const float sg = (r == 0) ? -1.0f : 1.0f;
            float p0 = rcp_fast(Af);
            float Z1 = fmaf(-Bf, p0, Af);
            float p1 = rcp_fast(Z1);
            u64 vv, ww;
            PACK2(vv, sg * p0, sg * p0);
            PACK2(ww, sg * p1, sg * p1);
            u64 fa = 0ull, fb = 0ull;
#pragma unroll
            for (int j = 0; j < PAIRS; j++) {
                u64 q;
                MUL2(q, t[j], vv);
                ADD2(nk[j], nk[j], q);
                FMA2(t[j], q, t[j], t[j]);
            }
#pragma unroll
            for (int j = 0; j < PAIRS; j++) {
                u64 b;
                MUL2(b, t[j], ww);
                ADD2(nk[j], nk[j], b);
                FMA2(t[j], b, b, b);
                ADD2(fa, fa, t[j]);
                FMA2(fb, t[j], t[j], fb);
            }
            {
                float lo, hi, pa, pb;
                UNPACK2(lo, hi, fa); pa = lo + hi;
                UNPACK2(lo, hi, fb); pb = lo + hi;
                u32 ua = redux_add_u32(f2u_rni(pa * NSCALE_F));
                u32 ub = redux_add_u32(f2u_rni(pb * SCALE_F));
                if (lane == 0) {
                    atomicAdd(&abank[2 * r],     ua);
                    atomicAdd(&abank[2 * r + 1], ub);
                }
            }
            __syncthreads();
            Af = u2f(abank[2 * r])     * ISCALE_F;
            Bf = u2f(abank[2 * r + 1]) * ISCALE_F;
        }

        // ---- staggered prologue for row+GRID (independent work) ----
        if (hasNext) {
            asm volatile("cp.async.wait_group 0;");
            u64 ma, mb;
            exp_pass(tile, tid, tn, ma, mb);
            prefetch_row(scores, g, row + 2 * GRID, tile, tid,
                         (row + 2 * GRID) < ROWS);
            warp_red_ab(ma, mb, redf, lane, wid);
        }
        if (tid < 14) (&acc[bank ^ 1][0][0])[tid] = 0u;

        // ---- body 5 (its barrier orders redf + acc zeroing) ----
#pragma unroll
        for (int r = 5; r < 7; r++) {
            float p0 = rcp_fast(Af);
            float Z1 = fmaf(-Bf, p0, Af);
            float p1 = rcp_fast(Z1);
            u64 vv, ww;
            PACK2(vv, p0, p0);
            PACK2(ww, p1, p1);
            u64 fa = 0ull, fb = 0ull;
#pragma unroll
            for (int j = 0; j < PAIRS; j++) {
                u64 q;
                MUL2(q, t[j], vv);
                ADD2(nk[j], nk[j], q);
                FMA2(t[j], q, t[j], t[j]);
            }
#pragma unroll
            for (int j = 0; j < PAIRS; j++) {
                u64 b;
                MUL2(b, t[j], ww);
                ADD2(nk[j], nk[j], b);
                FMA2(t[j], b, b, b);
                ADD2(fa, fa, t[j]);
                FMA2(fb, t[j], t[j], fb);
            }
            {
                float lo, hi, pa, pb;
                UNPACK2(lo, hi, fa); pa = lo + hi;
                UNPACK2(lo, hi, fb); pb = lo + hi;
                u32 ua = redux_add_u32(f2u_rni(pa * NSCALE_F));
                u32 ub = redux_add_u32(f2u_rni(pb * SCALE_F));
                if (lane == 0) {
                    atomicAdd(&abank[2 * r],     ua);
                    atomicAdd(&abank[2 * r + 1], ub);
                }
            }
            __syncthreads();
            if (r == 5 && hasNext) cross_red_ab(redf, lane, AfN, BfN);
            Af = u2f(abank[2 * r])     * ISCALE_F;
            Bf = u2f(abank[2 * r + 1]) * ISCALE_F;
        }

        // ---- body 7: iterA + final iteration (stored state negated) ----
        {
            float p0 = rcp_fast(Af);
            float Z1 = fmaf(-Bf, p0, Af);
            float p1 = rcp_fast(Z1);
            u64 vv, ww;
            PACK2(vv, p0, p0);
            PACK2(ww, p1, p1);
#pragma unroll
            for (int j = 0; j < PAIRS; j++) {
                u64 q;
                MUL2(q, t[j], vv);
                ADD2(nk[j], nk[j], q);
                FMA2(t[j], q, t[j], t[j]);
            }
#pragma unroll
            for (int j = 0; j < PAIRS; j++) {
                u64 q;
                MUL2(q, t[j], ww);
                ADD2(nk[j], nk[j], q);
            }
        }

        // ---- store khot = -nk ----
        float4* o4 = (float4*)(out + (size_t)row * NCOL);
#pragma unroll
        for (int c = 0; c < 4; c++) {
            float a0, a1, a2, a3;
            UNPACK2(a0, a1, nk[2 * c]);
            UNPACK2(a2, a3, nk[2 * c + 1]);
            float4 v; v.x = -a0; v.y = -a1; v.z = -a2; v.w = -a3;
            o4[tid + c * THREADS] = v;
        }

        // ---- rotate to next row ----
        if (hasNext) {
#pragma unroll
            for (int j = 0; j < PAIRS; j++) { t[j] = tn[j]; nk[j] = 0ull; }
            Af = AfN; Bf = BfN;
        }
        bank ^= 1;
    }
}

extern "C" void kernel_launch(void* const* d_in, const int* in_sizes, int n_in,
                              void* d_out, int out_size) {
    const float* scores = (const float*)d_in[0];
    const float* g      = (const float*)d_in[1];
    float* out          = (float*)d_out;
    cudaFuncSetAttribute(subset_op_kernel,
                         cudaFuncAttributeMaxDynamicSharedMemorySize, 2 * NCOL * 4);
    subset_op_kernel<<<GRID, THREADS, 2 * NCOL * 4>>>(scores, g, out);
}

// round 16
// speedup vs baseline: 1.3138x; 1.0023x over previous
#include <cuda_runtime.h>
#include <math_constants.h>
#include <cstdint>

// SubsetOperator soft k-hot (K=16, TAU=1), exp-domain, fixed shift (-10).
// R12 base (512 thr, 2 CTAs/SM, sign-flip renorm, u32 redux+atomic folds)
// + STAGGERED PROLOGUE VIA SMEM E-BUFFER: row r+1's exp pass runs mid-body of
// row r, result parked in a thread-private 32KB smem buffer (zero extra regs).
// Rotate = 8x LDS.64 of own data. Tile freed at stagger -> prefetch depth kept.

#define ROWS 4096
#define NCOL 8192
#define THREADS 512
#define PAIRS 8
#define GRID 296

typedef unsigned long long u64;
typedef unsigned int u32;

#define MUL2(d,a,b)    asm("mul.rn.f32x2 %0, %1, %2;"     : "=l"(d) : "l"(a), "l"(b))
#define ADD2(d,a,b)    asm("add.rn.f32x2 %0, %1, %2;"     : "=l"(d) : "l"(a), "l"(b))
#define FMA2(d,a,b,c)  asm("fma.rn.f32x2 %0, %1, %2, %3;" : "=l"(d) : "l"(a), "l"(b), "l"(c))
#define PACK2(d,lo,hi)   asm("mov.b64 %0, {%1, %2};" : "=l"(d) : "f"(lo), "f"(hi))
#define UNPACK2(lo,hi,s) asm("mov.b64 {%0, %1}, %2;" : "=f"(lo), "=f"(hi) : "l"(s))

__device__ __forceinline__ float rcp_fast(float x) {
    float r; asm("rcp.approx.f32 %0, %1;" : "=f"(r) : "f"(x)); return r;
}
__device__ __forceinline__ float ex2_fast(float x) {
    float r; asm("ex2.approx.f32 %0, %1;" : "=f"(r) : "f"(x)); return r;
}
__device__ __forceinline__ u32 f2u_rni(float x) {
    u32 u; asm("cvt.rni.u32.f32 %0, %1;" : "=r"(u) : "f"(x)); return u;
}
__device__ __forceinline__ float u2f(u32 u) {
    float x; asm("cvt.rn.f32.u32 %0, %1;" : "=f"(x) : "r"(u)); return x;
}
__device__ __forceinline__ u32 redux_add_u32(u32 v) {
    u32 d; asm("redux.sync.add.u32 %0, %1, 0xffffffff;" : "=r"(d) : "r"(v)); return d;
}

#define SCALE_F  268435456.0f
#define NSCALE_F -268435456.0f
#define ISCALE_F 3.725290298461914e-9f

__device__ __forceinline__ void cp16(u32 dst, const void* src) {
    asm volatile("cp.async.cg.shared.global [%0], [%1], 16;" :: "r"(dst), "l"(src));
}

__device__ __forceinline__ void prefetch_row(const float* s, const float* gg,
                                             int row, float* tile, int tid, bool valid) {
    if (valid) {
        const float4* s4 = (const float4*)(s + (size_t)row * NCOL);
        const float4* g4 = (const float4*)(gg + (size_t)row * NCOL);
        u32 ds = (u32)__cvta_generic_to_shared(tile);
#pragma unroll
        for (int c = 0; c < 4; c++) {
            cp16(ds + (u32)(tid + c * THREADS) * 16u,                  s4 + tid + c * THREADS);
            cp16(ds + (u32)NCOL * 4u + (u32)(tid + c * THREADS) * 16u, g4 + tid + c * THREADS);
        }
    }
    asm volatile("cp.async.commit_group;");
}

// exp pass into registers (+ packed (A,B) moment partials)
__device__ __forceinline__ void exp_pass_reg(const float* tile, int tid,
                                             u64* t, u64& ma, u64& mb) {
    const float4* ts4 = (const float4*)tile;
    const float4* tg4 = (const float4*)(tile + NCOL);
    const float L2E = 1.4426950408889634f;
    const float CC  = -10.0f * L2E;
    ma = 0ull; mb = 0ull;
#pragma unroll
    for (int c = 0; c < 4; c++) {
        const int i4 = tid + c * THREADS;
        float4 a = ts4[i4];
        float4 b = tg4[i4];
        float e0 = ex2_fast(fmaf(a.x + b.x, L2E, CC));
        float e1 = ex2_fast(fmaf(a.y + b.y, L2E, CC));
        float e2 = ex2_fast(fmaf(a.z + b.z, L2E, CC));
        float e3 = ex2_fast(fmaf(a.w + b.w, L2E, CC));
        PACK2(t[2 * c],     e0, e1);
        PACK2(t[2 * c + 1], e2, e3);
        ADD2(ma, ma, t[2 * c]);
        ADD2(ma, ma, t[2 * c + 1]);
        FMA2(mb, t[2 * c],     t[2 * c],     mb);
        FMA2(mb, t[2 * c + 1], t[2 * c + 1], mb);
    }
}

// exp pass into smem e-buffer (thread-private scratch; no regs held)
__device__ __forceinline__ void exp_pass_store(const float* tile, u64* ebuf, int tid,
                                               u64& ma, u64& mb) {
    const float4* ts4 = (const float4*)tile;
    const float4* tg4 = (const float4*)(tile + NCOL);
    const float L2E = 1.4426950408889634f;
    const float CC  = -10.0f * L2E;
    ma = 0ull; mb = 0ull;
#pragma unroll
    for (int c = 0; c < 4; c++) {
        const int i4 = tid + c * THREADS;
        float4 a = ts4[i4];
        float4 b = tg4[i4];
        float e0 = ex2_fast(fmaf(a.x + b.x, L2E, CC));
        float e1 = ex2_fast(fmaf(a.y + b.y, L2E, CC));
        float e2 = ex2_fast(fmaf(a.z + b.z, L2E, CC));
        float e3 = ex2_fast(fmaf(a.w + b.w, L2E, CC));
        u64 t0, t1;
        PACK2(t0, e0, e1);
        PACK2(t1, e2, e3);
        ebuf[(2 * c) * THREADS + tid]     = t0;   // STS.64, lane-stride 8B
        ebuf[(2 * c + 1) * THREADS + tid] = t1;
        ADD2(ma, ma, t0);
        ADD2(ma, ma, t1);
        FMA2(mb, t0, t0, mb);
        FMA2(mb, t1, t1, mb);
    }
}

__device__ __forceinline__ void warp_red_ab(u64 ma, u64 mb, float2* slot,
                                            int lane, int wid) {
    float lo, hi, x, y;
    UNPACK2(lo, hi, ma); x = lo + hi;
    UNPACK2(lo, hi, mb); y = lo + hi;
    u64 u; PACK2(u, x, y);
#pragma unroll
    for (int o = 16; o > 0; o >>= 1) {
        u64 tsh = __shfl_xor_sync(0xffffffffu, u, o);
        ADD2(u, u, tsh);
    }
    if (lane == 0) { float2 q; UNPACK2(q.x, q.y, u); slot[wid] = q; }
}

__device__ __forceinline__ void cross_red_ab(const float2* buf, int lane,
                                             float& A, float& B) {
    float2 v = buf[lane & 15];
    u64 u; PACK2(u, v.x, v.y);
#pragma unroll
    for (int o = 8; o > 0; o >>= 1) {
        u64 tsh = __shfl_xor_sync(0xffffffffu, u, o);
        ADD2(u, u, tsh);
    }
    UNPACK2(A, B, u);
}

// one 2-iteration body with fold (sign-flip renorm; sg=+1 when state negated)
__device__ __forceinline__ void body_fold(u64* t, u64* nk, float Af, float Bf,
                                          float sg, u32* accA, u32* accB,
                                          int lane) {
    float p0 = rcp_fast(Af);
    float Z1 = fmaf(-Bf, p0, Af);
    float p1 = rcp_fast(Z1);
    u64 vv, ww;
    PACK2(vv, sg * p0, sg * p0);
    PACK2(ww, sg * p1, sg * p1);
    u64 fa = 0ull, fb = 0ull;
#pragma unroll
    for (int j = 0; j < PAIRS; j++) {
        u64 q;
        MUL2(q, t[j], vv);
        ADD2(nk[j], nk[j], q);
        FMA2(t[j], q, t[j], t[j]);
    }
#pragma unroll
    for (int j = 0; j < PAIRS; j++) {
        u64 b;
        MUL2(b, t[j], ww);
        ADD2(nk[j], nk[j], b);
        FMA2(t[j], b, b, b);          // -(renormalized next state)
        ADD2(fa, fa, t[j]);
        FMA2(fb, t[j], t[j], fb);
    }
    float lo, hi, pa, pb;
    UNPACK2(lo, hi, fa); pa = lo + hi;
    UNPACK2(lo, hi, fb); pb = lo + hi;
    u32 ua = redux_add_u32(f2u_rni(pa * NSCALE_F));
    u32 ub = redux_add_u32(f2u_rni(pb * SCALE_F));
    if (lane == 0) {
        atomicAdd(accA, ua);
        atomicAdd(accB, ub);
    }
}

__global__ void __launch_bounds__(THREADS, 2)
subset_op_kernel(const float* __restrict__ scores,
                 const float* __restrict__ g,
                 float* __restrict__ out) {
    extern __shared__ __align__(16) float tile[];   // s(32K) | g(32K) | ebuf(32K)
    __shared__ __align__(16) float2 redf[16];
    __shared__ __align__(8)  u32 acc[2][7][2];

    u64* const ebuf = (u64*)(tile + 2 * NCOL);

    const int tid  = threadIdx.x;
    const int lane = tid & 31;
    const int wid  = tid >> 5;

    int row = blockIdx.x;
    prefetch_row(scores, g, row, tile, tid, true);

    // ---- startup prologue (first row into registers) ----
    u64 t[PAIRS], nk[PAIRS];
    float Af, Bf;
    {
        asm volatile("cp.async.wait_group 0;");
        __syncthreads();
        if (tid < 14) (&acc[0][0][0])[tid] = 0u;
        u64 ma, mb;
        exp_pass_reg(tile, tid, t, ma, mb);
#pragma unroll
        for (int j = 0; j < PAIRS; j++) nk[j] = 0ull;
        prefetch_row(scores, g, row + GRID, tile, tid, (row + GRID) < ROWS);
        warp_red_ab(ma, mb, redf, lane, wid);
        __syncthreads();
        cross_red_ab(redf, lane, Af, Bf);
    }

    int bank = 0;
    for (; row < ROWS; row += GRID) {
        const bool hasNext = (row + GRID) < ROWS;
        float AfN = 0.0f, BfN = 0.0f;
        u32* const abank = &acc[bank][0][0];

        // ---- bodies 0..4 ----
#pragma unroll
        for (int r = 0; r < 5; r++) {
            const float sg = (r == 0) ? -1.0f : 1.0f;
            body_fold(t, nk, Af, Bf, sg, &abank[2 * r], &abank[2 * r + 1], lane);
            __syncthreads();
            Af = u2f(abank[2 * r])     * ISCALE_F;
            Bf = u2f(abank[2 * r + 1]) * ISCALE_F;
        }

        // ---- staggered prologue for row+GRID: exp -> smem e-buffer ----
        if (hasNext) {
            asm volatile("cp.async.wait_group 0;");
            u64 ma, mb;
            exp_pass_store(tile, ebuf, tid, ma, mb);
            warp_red_ab(ma, mb, redf, lane, wid);
        }
        if (tid < 14) (&acc[bank ^ 1][0][0])[tid] = 0u;

        // ---- bodies 5..6 (body-5 barrier orders stagger; prefetch after) ----
#pragma unroll
        for (int r = 5; r < 7; r++) {
            body_fold(t, nk, Af, Bf, 1.0f, &abank[2 * r], &abank[2 * r + 1], lane);
            __syncthreads();
            if (r == 5) {
                // tile fully consumed by the staggered exp -> safe to refill
                prefetch_row(scores, g, row + 2 * GRID, tile, tid,
                             (row + 2 * GRID) < ROWS);
                if (hasNext) cross_red_ab(redf, lane, AfN, BfN);
            }
            Af = u2f(abank[2 * r])     * ISCALE_F;
            Bf = u2f(abank[2 * r + 1]) * ISCALE_F;
        }

        // ---- body 7: iterA + final iteration ----
        {
            float p0 = rcp_fast(Af);
            float Z1 = fmaf(-Bf, p0, Af);
            float p1 = rcp_fast(Z1);
            u64 vv, ww;
            PACK2(vv, p0, p0);
            PACK2(ww, p1, p1);
#pragma unroll
            for (int j = 0; j < PAIRS; j++) {
                u64 q;
                MUL2(q, t[j], vv);
                ADD2(nk[j], nk[j], q);
                FMA2(t[j], q, t[j], t[j]);
            }
#pragma unroll
            for (int j = 0; j < PAIRS; j++) {
                u64 q;
                MUL2(q, t[j], ww);
                ADD2(nk[j], nk[j], q);
            }
        }

        // ---- store khot = -nk ----
        float4* o4 = (float4*)(out + (size_t)row * NCOL);
#pragma unroll
        for (int c = 0; c < 4; c++) {
            float a0, a1, a2, a3;
            UNPACK2(a0, a1, nk[2 * c]);
            UNPACK2(a2, a3, nk[2 * c + 1]);
            float4 v; v.x = -a0; v.y = -a1; v.z = -a2; v.w = -a3;
            o4[tid + c * THREADS] = v;
        }

        // ---- rotate: reload own e from smem scratch (thread-private) ----
        if (hasNext) {
#pragma unroll
            for (int j = 0; j < PAIRS; j++) {
                t[j] = ebuf[j * THREADS + tid];
                nk[j] = 0ull;
            }
            Af = AfN; Bf = BfN;
        }
        bank ^= 1;
    }
}

extern "C" void kernel_launch(void* const* d_in, const int* in_sizes, int n_in,
                              void* d_out, int out_size) {
    const float* scores = (const float*)d_in[0];
    const float* g      = (const float*)d_in[1];
    float* out          = (float*)d_out;
    cudaFuncSetAttribute(subset_op_kernel,
                         cudaFuncAttributeMaxDynamicSharedMemorySize, 3 * NCOL * 4);
    subset_op_kernel<<<GRID, THREADS, 3 * NCOL * 4>>>(scores, g, out);
}